// round 1
// baseline (speedup 1.0000x reference)
#include <cuda_runtime.h>
#include <cuda_bf16.h>

#define TAGS 128

// Packed f32x2 FMA/ADD (Blackwell): d.lo = a.lo*b.lo + d.lo, d.hi likewise.
__device__ __forceinline__ void fma2(double &acc, double a, double b) {
    asm("fma.rn.f32x2 %0, %1, %2, %0;" : "+d"(acc) : "d"(a), "d"(b));
}
__device__ __forceinline__ double add2(double a, double b) {
    double d;
    asm("add.rn.f32x2 %0, %1, %2;" : "=d"(d) : "d"(a), "d"(b));
    return d;
}

__global__ void __launch_bounds__(TAGS, 1) crf_logz_kernel(
    const float* __restrict__ emissions,     // [B, T, 1, TAGS]
    const int*   __restrict__ token_sizes,   // [B]
    const float* __restrict__ transitions,   // [1, 1, TAGS, TAGS]
    const float* __restrict__ head_t,        // [1, 1, TAGS]
    const float* __restrict__ last_t,        // [1, 1, TAGS]
    float*       __restrict__ out,           // [B, 1]
    int T)
{
    __shared__ __align__(16) float pbuf[2][TAGS];
    __shared__ float red[TAGS];

    const int n = threadIdx.x;      // output tag owned by this thread
    const int b = blockIdx.x;       // batch element owned by this CTA
    const int len = token_sizes[b];
    const float* emb = emissions + (size_t)b * T * TAGS;

    // exp(transitions) column n, packed into f32x2 register pairs.
    double T2[TAGS / 2];
#pragma unroll
    for (int i = 0; i < TAGS / 2; ++i) {
        float2 f;
        f.x = __expf(transitions[(2 * i    ) * TAGS + n]);
        f.y = __expf(transitions[(2 * i + 1) * TAGS + n]);
        T2[i] = *reinterpret_cast<double*>(&f);
    }

    // alpha_0 = head + emissions[0]  ->  p = exp(alpha), off = 0
    pbuf[0][n] = __expf(head_t[n] + emb[n]);
    double off = 0.0;
    int cur = 0;

    // One step of the recurrence in the probability domain.
    // Invariant on entry: pbuf[cur] holds p_t (all threads past the barrier
    // from the previous step's write). Exactly ONE __syncthreads per step:
    // writes go to the other buffer, so fast threads never race readers.
    auto dostep = [&](float emv) {
        __syncthreads();
        const float* pc = pbuf[cur];
        float c  = pc[0];                    // broadcast scalar for rescale
        float r  = __fdividef(1.0f, c);
        float lc = __logf(c);
        float E  = __expf(emv);

        const double2* pd = reinterpret_cast<const double2*>(pc);
        double a0 = 0.0, a1 = 0.0, a2 = 0.0, a3 = 0.0;
#pragma unroll
        for (int i = 0; i < TAGS / 8; ++i) {
            double2 u = pd[2 * i];
            double2 w = pd[2 * i + 1];
            fma2(a0, u.x, T2[4 * i    ]);
            fma2(a1, u.y, T2[4 * i + 1]);
            fma2(a2, w.x, T2[4 * i + 2]);
            fma2(a3, w.y, T2[4 * i + 3]);
        }
        double s2 = add2(add2(a0, a1), add2(a2, a3));
        float2 sf = *reinterpret_cast<float2*>(&s2);
        float s = sf.x + sf.y;               // s[n] = sum_m p[m] * Texp[m][n]

        pbuf[cur ^ 1][n] = s * r * E;        // p_{t+1}[n], rescaled by 1/p_t[0]
        off += (double)lc;                   // alpha = off + log p
        cur ^= 1;
    };

    // Main loop, unrolled x4 with a 4-step emission prefetch pipeline
    // (~750 cycles of cover > 577-cycle DRAM latency).
    int t = 1;
    float f0 = emb[1 * TAGS + n];
    float f1 = emb[2 * TAGS + n];
    float f2 = emb[3 * TAGS + n];
    float f3 = emb[4 * TAGS + n];

    for (; t + 4 <= len; t += 4) {
        int tp = t + 4;
        int i0 = (tp     < T) ? tp     : T - 1;
        int i1 = (tp + 1 < T) ? tp + 1 : T - 1;
        int i2 = (tp + 2 < T) ? tp + 2 : T - 1;
        int i3 = (tp + 3 < T) ? tp + 3 : T - 1;
        float g0 = emb[i0 * TAGS + n];
        float g1 = emb[i1 * TAGS + n];
        float g2 = emb[i2 * TAGS + n];
        float g3 = emb[i3 * TAGS + n];
        dostep(f0);
        dostep(f1);
        dostep(f2);
        dostep(f3);
        f0 = g0; f1 = g1; f2 = g2; f3 = g3;
    }
    if (t < len) { dostep(f0); ++t; }
    if (t < len) { dostep(f1); ++t; }
    if (t < len) { dostep(f2); ++t; }

    // Finalize: out[b] = off + log( sum_n p[n] * exp(last[n]) )
    __syncthreads();
    red[n] = pbuf[cur][n] * __expf(last_t[n]);
    __syncthreads();
#pragma unroll
    for (int sft = TAGS / 2; sft > 0; sft >>= 1) {
        if (n < sft) red[n] += red[n + sft];
        __syncthreads();
    }
    if (n == 0) out[b] = (float)(off + (double)__logf(red[0]));
}

extern "C" void kernel_launch(void* const* d_in, const int* in_sizes, int n_in,
                              void* d_out, int out_size) {
    const float* em = (const float*)d_in[0];
    const int*   ts = (const int*)  d_in[1];
    const float* tr = (const float*)d_in[2];
    const float* hd = (const float*)d_in[3];
    const float* lt = (const float*)d_in[4];
    float* out = (float*)d_out;

    int B = in_sizes[1];                       // token_sizes count
    int T = in_sizes[0] / (B * TAGS);          // C == 1

    crf_logz_kernel<<<B, TAGS>>>(em, ts, tr, hd, lt, out, T);
}

// round 2
// speedup vs baseline: 1.3039x; 1.3039x over previous
#include <cuda_runtime.h>
#include <cuda_bf16.h>

#define TAGS 128

// Packed f32x2 FMA/ADD (Blackwell): lane-wise on a register pair.
__device__ __forceinline__ void fma2(double &acc, double a, double b) {
    asm("fma.rn.f32x2 %0, %1, %2, %0;" : "+d"(acc) : "d"(a), "d"(b));
}
__device__ __forceinline__ double add2(double a, double b) {
    double d;
    asm("add.rn.f32x2 %0, %1, %2;" : "=d"(d) : "d"(a), "d"(b));
    return d;
}

__global__ void __launch_bounds__(TAGS, 1) crf_logz_kernel(
    const float* __restrict__ emissions,     // [B, T, 1, TAGS]
    const int*   __restrict__ token_sizes,   // [B]
    const float* __restrict__ transitions,   // [1, 1, TAGS, TAGS]
    const float* __restrict__ head_t,        // [1, 1, TAGS]
    const float* __restrict__ last_t,        // [1, 1, TAGS]
    float*       __restrict__ out,           // [B, 1]
    int T)
{
    __shared__ __align__(16) float pbuf[2][TAGS];
    __shared__ float red[TAGS];

    const int n = threadIdx.x;      // output tag owned by this thread
    const int b = blockIdx.x;       // batch element owned by this CTA
    const int len = token_sizes[b];
    const float* emb = emissions + (size_t)b * T * TAGS;

    // exp(transitions) column n, packed into f32x2 register pairs.
    double T2[TAGS / 2];
#pragma unroll
    for (int i = 0; i < TAGS / 2; ++i) {
        float2 f;
        f.x = __expf(transitions[(2 * i    ) * TAGS + n]);
        f.y = __expf(transitions[(2 * i + 1) * TAGS + n]);
        T2[i] = *reinterpret_cast<double*>(&f);
    }

    // alpha_0 = head + emissions[0]  ->  p = exp(alpha), etot = 0
    pbuf[0][n] = __expf(head_t[n] + emb[n]);
    int etot = 0;        // sum of binary exponents stripped from p; exact
    int cur = 0;

    // One recurrence step in the probability domain. E = exp(emission[t][n])
    // is PRECOMPUTED in the prefetch stage (off the critical path).
    // Rescale by 2^{-exponent(p[0])}: pure integer ops, no MUFU, no FP64.
    // Exactly one __syncthreads per step (double-buffered p).
    auto dostep = [&](float E) {
        __syncthreads();
        const float* pc = pbuf[cur];
        float c = pc[0];                             // broadcast scalar
        int   e = ((__float_as_int(c) >> 23) & 255) - 127;
        float scale = __int_as_float((127 - e) << 23);   // 2^{-e}

        const double2* pd = reinterpret_cast<const double2*>(pc);
        double a0 = 0.0, a1 = 0.0, a2 = 0.0, a3 = 0.0;
#pragma unroll
        for (int i = 0; i < TAGS / 8; ++i) {
            double2 u = pd[2 * i];
            double2 w = pd[2 * i + 1];
            fma2(a0, u.x, T2[4 * i    ]);
            fma2(a1, u.y, T2[4 * i + 1]);
            fma2(a2, w.x, T2[4 * i + 2]);
            fma2(a3, w.y, T2[4 * i + 3]);
        }
        double s2 = add2(add2(a0, a1), add2(a2, a3));
        float2 sf = *reinterpret_cast<float2*>(&s2);

        pbuf[cur ^ 1][n] = (sf.x + sf.y) * (E * scale);  // p_{t+1}[n]
        etot += e;
        cur ^= 1;
    };

    // Main loop, unrolled x4. Prefetch emissions 4 steps ahead AND exp()
    // them immediately — MUFU work lands 4 steps (~800 cyc) before use.
    int t = 1;
    float E0 = __expf(emb[((1 < T) ? 1 : T - 1) * TAGS + n]);
    float E1 = __expf(emb[((2 < T) ? 2 : T - 1) * TAGS + n]);
    float E2 = __expf(emb[((3 < T) ? 3 : T - 1) * TAGS + n]);
    float E3 = __expf(emb[((4 < T) ? 4 : T - 1) * TAGS + n]);

    for (; t + 4 <= len; t += 4) {
        int tp = t + 4;
        int i0 = (tp     < T) ? tp     : T - 1;
        int i1 = (tp + 1 < T) ? tp + 1 : T - 1;
        int i2 = (tp + 2 < T) ? tp + 2 : T - 1;
        int i3 = (tp + 3 < T) ? tp + 3 : T - 1;
        float G0 = __expf(emb[i0 * TAGS + n]);
        float G1 = __expf(emb[i1 * TAGS + n]);
        float G2 = __expf(emb[i2 * TAGS + n]);
        float G3 = __expf(emb[i3 * TAGS + n]);
        dostep(E0);
        dostep(E1);
        dostep(E2);
        dostep(E3);
        E0 = G0; E1 = G1; E2 = G2; E3 = G3;
    }
    if (t < len) { dostep(E0); ++t; }
    if (t < len) { dostep(E1); ++t; }
    if (t < len) { dostep(E2); ++t; }

    // Finalize: out[b] = etot*ln2 + log( sum_n p[n] * exp(last[n]) )
    __syncthreads();
    red[n] = pbuf[cur][n] * __expf(last_t[n]);
    __syncthreads();
#pragma unroll
    for (int sft = TAGS / 2; sft > 0; sft >>= 1) {
        if (n < sft) red[n] += red[n + sft];
        __syncthreads();
    }
    if (n == 0)
        out[b] = (float)((double)etot * 0.6931471805599453 +
                         (double)__logf(red[0]));
}

extern "C" void kernel_launch(void* const* d_in, const int* in_sizes, int n_in,
                              void* d_out, int out_size) {
    const float* em = (const float*)d_in[0];
    const int*   ts = (const int*)  d_in[1];
    const float* tr = (const float*)d_in[2];
    const float* hd = (const float*)d_in[3];
    const float* lt = (const float*)d_in[4];
    float* out = (float*)d_out;

    int B = in_sizes[1];                       // token_sizes count
    int T = in_sizes[0] / (B * TAGS);          // C == 1

    crf_logz_kernel<<<B, TAGS>>>(em, ts, tr, hd, lt, out, T);
}